// round 9
// baseline (speedup 1.0000x reference)
#include <cuda_runtime.h>
#include <math.h>
#include <stdint.h>

#define BMS     64        // B*M sequences
#define NPATCH  511
#define DMODEL  64
#define NHEAD   8
#define DHEAD   8
#define DFF     256
#define PATCH   16
#define PREDL   96
#define UPART   35
#define UTOP    35
#define ROWS    (BMS*NPATCH)   // 32704

// ---------------- scratch (device globals; no runtime allocation) ----------------
__device__ float g_patch[ROWS*PATCH];
__device__ float g_z  [ROWS*DMODEL];
__device__ float g_q  [ROWS*DMODEL];
__device__ float g_k  [ROWS*DMODEL];
__device__ float g_v  [ROWS*DMODEL];
__device__ float g_ao [ROWS*DMODEL];
__device__ float g_tmp[ROWS*DMODEL];
__device__ float g_x1 [ROWS*DMODEL];
__device__ float g_ffn[ROWS*DFF];
__device__ int   g_sampidx[2*NPATCH*UPART];

// ---------------- Threefry-2x32 (JAX prng) ----------------
__device__ __forceinline__ void tf2x32(uint32_t k0, uint32_t k1,
                                       uint32_t x0, uint32_t x1,
                                       uint32_t& o0, uint32_t& o1) {
    uint32_t ks0 = k0, ks1 = k1, ks2 = k0 ^ k1 ^ 0x1BD11BDAu;
    x0 += ks0; x1 += ks1;
    const int RA[4] = {13,15,26,6};
    const int RB[4] = {17,29,16,24};
    uint32_t ks[3] = {ks0, ks1, ks2};
#pragma unroll
    for (int g = 0; g < 5; ++g) {
        const int* R = (g & 1) ? RB : RA;
#pragma unroll
        for (int i = 0; i < 4; ++i) {
            x0 += x1;
            x1 = (x1 << R[i]) | (x1 >> (32 - R[i]));
            x1 ^= x0;
        }
        x0 += ks[(g+1)%3];
        x1 += ks[(g+2)%3] + (uint32_t)(g+1);
    }
    o0 = x0; o1 = x1;
}

// jax.random.key(1) -> (0,1); fold_in(key,e); split (fold-like, partitionable);
// random_bits32[i] = b1(0,i) ^ b2(0,i); randint over [0,511).
__global__ void idx_kernel(int* __restrict__ out) {
    int e = blockIdx.x;
    uint32_t ke0, ke1;
    tf2x32(0u, 1u, 0u, (uint32_t)e, ke0, ke1);          // fold_in(key(1), e)
    uint32_t k10, k11, k20, k21;
    tf2x32(ke0, ke1, 0u, 0u, k10, k11);                 // split -> k1
    tf2x32(ke0, ke1, 0u, 1u, k20, k21);                 // split -> k2
    const uint32_t span = 511u;
    uint32_t mult = (1u << 16) % span;                  // 128
    mult = (mult * mult) % span;                        // 32
    for (int i = threadIdx.x; i < NPATCH*UPART; i += blockDim.x) {
        uint32_t a0, a1, b0, b1;
        tf2x32(k10, k11, 0u, (uint32_t)i, a0, a1);
        tf2x32(k20, k21, 0u, (uint32_t)i, b0, b1);
        uint32_t hb = a0 ^ a1;
        uint32_t lb = b0 ^ b1;
        uint32_t off = ((hb % span) * mult + (lb % span)) % span;
        out[e*NPATCH*UPART + i] = (int)off;
    }
}

// ---------------- patch gather ----------------
// patches[s,n,p] = x_enc[b, n*8+p, m], s=b*8+m, x_enc (8,4096,8)
__global__ void patch_kernel(const float* __restrict__ x_enc, float* __restrict__ outp) {
    int i = blockIdx.x * blockDim.x + threadIdx.x;
    if (i >= ROWS*PATCH) return;
    int p = i & 15;
    int n = (i >> 4) % NPATCH;
    int s = i / (NPATCH*PATCH);
    int b = s >> 3, m = s & 7;
    outp[i] = x_enc[(b*4096 + n*8 + p)*8 + m];
}

// ---------------- tiled SGEMM: C(RxD) = A(RxK) @ W(DxK)^T + bias, opt GELU ----------------
__device__ __forceinline__ float gelu_exact(float x) {
    return 0.5f * x * (1.0f + erff(x * 0.7071067811865476f));
}

__global__ __launch_bounds__(256) void gemm_kernel(
    const float* __restrict__ A, const float* __restrict__ W,
    const float* __restrict__ bias, float* __restrict__ C,
    int K, int D, int act)
{
    __shared__ float As[16][68];
    __shared__ float Ws[16][68];
    const int row0 = blockIdx.x * 64;
    const int col0 = blockIdx.y * 64;
    const int tid = threadIdx.x;
    const int tx = tid & 15;       // 4-col group
    const int ty = tid >> 4;       // 4-row group
    float acc[4][4];
#pragma unroll
    for (int j = 0; j < 4; ++j) {
        float bv = bias[col0 + tx*4 + j];
#pragma unroll
        for (int i = 0; i < 4; ++i) acc[i][j] = bv;
    }
    // per-thread staging indices for the 64x16 tiles: 4 elements each of A and W
    const int lr = tid >> 2;            // 0..63 (row within tile)
    const int lk = (tid & 3) * 4;       // 0,4,8,12 (k-offset, 4 consecutive)
    for (int k0 = 0; k0 < K; k0 += 16) {
        // front-batched loads (2x LDG.128 per thread)
        float4 av4 = *(const float4*)&A[(size_t)(row0 + lr)*K + k0 + lk];
        float4 wv4 = *(const float4*)&W[(size_t)(col0 + lr)*K + k0 + lk];
        As[lk+0][lr] = av4.x; As[lk+1][lr] = av4.y; As[lk+2][lr] = av4.z; As[lk+3][lr] = av4.w;
        Ws[lk+0][lr] = wv4.x; Ws[lk+1][lr] = wv4.y; Ws[lk+2][lr] = wv4.z; Ws[lk+3][lr] = wv4.w;
        __syncthreads();
#pragma unroll
        for (int kl = 0; kl < 16; ++kl) {
            float4 a = *(const float4*)&As[kl][ty*4];
            float4 w = *(const float4*)&Ws[kl][tx*4];
            float av[4] = {a.x, a.y, a.z, a.w};
            float wv[4] = {w.x, w.y, w.z, w.w};
#pragma unroll
            for (int i = 0; i < 4; ++i)
#pragma unroll
                for (int j = 0; j < 4; ++j)
                    acc[i][j] += av[i] * wv[j];
        }
        __syncthreads();
    }
#pragma unroll
    for (int i = 0; i < 4; ++i) {
        int r = row0 + ty*4 + i;
#pragma unroll
        for (int j = 0; j < 4; ++j) {
            float vv = acc[i][j];
            if (act == 1) vv = gelu_exact(vv);
            C[(size_t)r*D + col0 + tx*4 + j] = vv;
        }
    }
}

// ---------------- ProbSparse attention: one block per (s,h) ----------------
__global__ __launch_bounds__(256) void attn_kernel(
    const float* __restrict__ q, const float* __restrict__ k,
    const float* __restrict__ v, const int* __restrict__ sidx,
    float* __restrict__ ao)
{
    const int s = blockIdx.x >> 3;
    const int h = blockIdx.x & 7;
    const size_t base = (size_t)(s*NPATCH)*DMODEL + h*DHEAD;

    __shared__ float4 ksA[NPATCH], ksB[NPATCH], vsA[NPATCH], vsB[NPATCH];
    __shared__ float  sp[NPATCH];
    __shared__ float  rv[256];
    __shared__ int    ri[256];
    __shared__ int    topn[UTOP];
    __shared__ float  vmean[8];
    __shared__ float  sred[256];

    const int tid = threadIdx.x;

    // load K/V head into shared (split into two float4 lanes: conflict-free)
    float pv[8] = {0,0,0,0,0,0,0,0};
    for (int n = tid; n < NPATCH; n += 256) {
        const float4* kp = (const float4*)(k + base + (size_t)n*DMODEL);
        ksA[n] = kp[0]; ksB[n] = kp[1];
        const float4* vp = (const float4*)(v + base + (size_t)n*DMODEL);
        float4 v0 = vp[0], v1 = vp[1];
        vsA[n] = v0; vsB[n] = v1;
        pv[0]+=v0.x; pv[1]+=v0.y; pv[2]+=v0.z; pv[3]+=v0.w;
        pv[4]+=v1.x; pv[5]+=v1.y; pv[6]+=v1.z; pv[7]+=v1.w;
    }
    // vmean = sum / 511
#pragma unroll
    for (int c = 0; c < 8; ++c) {
        __syncthreads();
        sred[tid] = pv[c];
        __syncthreads();
        for (int off = 128; off > 0; off >>= 1) {
            if (tid < off) sred[tid] += sred[tid + off];
            __syncthreads();
        }
        if (tid == 0) vmean[c] = sred[0] / 511.0f;
    }
    __syncthreads();

    // sparsity measure per query
    for (int n = tid; n < NPATCH; n += 256) {
        const float4* qp = (const float4*)(q + base + (size_t)n*DMODEL);
        float4 qa = qp[0], qb = qp[1];
        float mx = -INFINITY, sm = 0.f;
        const int* ip = sidx + n*UPART;
#pragma unroll 5
        for (int j = 0; j < UPART; ++j) {
            int kk = ip[j];
            float4 ka = ksA[kk], kb = ksB[kk];
            float d = qa.x*ka.x + qa.y*ka.y + qa.z*ka.z + qa.w*ka.w
                    + qb.x*kb.x + qb.y*kb.y + qb.z*kb.z + qb.w*kb.w;
            mx = fmaxf(mx, d);
            sm += d;
        }
        sp[n] = mx - sm / 511.0f;
    }
    __syncthreads();

    // top-35 (ties -> lower index, matching lax.top_k)
    for (int t = 0; t < UTOP; ++t) {
        float bv = -INFINITY; int bi = 0x7fffffff;
        for (int n = tid; n < NPATCH; n += 256)
            if (sp[n] > bv) { bv = sp[n]; bi = n; }
        rv[tid] = bv; ri[tid] = bi;
        __syncthreads();
        for (int off = 128; off > 0; off >>= 1) {
            if (tid < off) {
                float ov = rv[tid+off]; int oi = ri[tid+off];
                if (ov > rv[tid] || (ov == rv[tid] && oi < ri[tid])) { rv[tid] = ov; ri[tid] = oi; }
            }
            __syncthreads();
        }
        if (tid == 0) { topn[t] = ri[0]; sp[ri[0]] = -INFINITY; }
        __syncthreads();
    }

    // default output: mean of V
    for (int i = tid; i < NPATCH*8; i += 256) {
        int n = i >> 3, c = i & 7;
        ao[base + (size_t)n*DMODEL + c] = vmean[c];
    }
    __syncthreads();

    // full attention for selected queries: one warp per query
    const float scale = 0.3535533905932738f;  // rsqrt(8)
    const int wid = tid >> 5, lane = tid & 31;
    for (int t = wid; t < UTOP; t += 8) {
        int n = topn[t];
        const float4* qp = (const float4*)(q + base + (size_t)n*DMODEL);
        float4 qa = qp[0], qb = qp[1];
        float mx = -INFINITY;
        for (int kk = lane; kk < NPATCH; kk += 32) {
            float4 ka = ksA[kk], kb = ksB[kk];
            float d = (qa.x*ka.x + qa.y*ka.y + qa.z*ka.z + qa.w*ka.w
                     + qb.x*kb.x + qb.y*kb.y + qb.z*kb.z + qb.w*kb.w) * scale;
            mx = fmaxf(mx, d);
        }
#pragma unroll
        for (int off = 16; off > 0; off >>= 1)
            mx = fmaxf(mx, __shfl_xor_sync(0xffffffffu, mx, off));
        float sm = 0.f;
        float ac[8] = {0,0,0,0,0,0,0,0};
        for (int kk = lane; kk < NPATCH; kk += 32) {
            float4 ka = ksA[kk], kb = ksB[kk];
            float d = (qa.x*ka.x + qa.y*ka.y + qa.z*ka.z + qa.w*ka.w
                     + qb.x*kb.x + qb.y*kb.y + qb.z*kb.z + qb.w*kb.w) * scale;
            float e = expf(d - mx);
            sm += e;
            float4 va = vsA[kk], vb = vsB[kk];
            ac[0]+=e*va.x; ac[1]+=e*va.y; ac[2]+=e*va.z; ac[3]+=e*va.w;
            ac[4]+=e*vb.x; ac[5]+=e*vb.y; ac[6]+=e*vb.z; ac[7]+=e*vb.w;
        }
#pragma unroll
        for (int off = 16; off > 0; off >>= 1) {
            sm += __shfl_xor_sync(0xffffffffu, sm, off);
#pragma unroll
            for (int c = 0; c < 8; ++c)
                ac[c] += __shfl_xor_sync(0xffffffffu, ac[c], off);
        }
        if (lane == 0) {
            float inv = 1.0f / sm;
            float* op = ao + base + (size_t)n*DMODEL;
#pragma unroll
            for (int c = 0; c < 8; ++c) op[c] = ac[c] * inv;
        }
    }
}

// ---------------- LayerNorm over DM=64: out = LN(a + b?) * g + beta ----------------
__global__ __launch_bounds__(256) void ln_kernel(
    const float* __restrict__ a, const float* __restrict__ b,
    const float* __restrict__ g, const float* __restrict__ beta,
    float* __restrict__ out)
{
    const int tid  = threadIdx.x;
    const int row  = blockIdx.x*4 + (tid >> 6);
    const int lane = tid & 63;
    __shared__ float sh[256];
    const size_t off = (size_t)row*DMODEL + lane;
    float x = a[off];
    if (b) x += b[off];
    sh[tid] = x;
    __syncthreads();
    for (int o = 32; o > 0; o >>= 1) {
        if (lane < o) sh[tid] += sh[tid + o];
        __syncthreads();
    }
    float mu = sh[tid & ~63] / 64.0f;
    __syncthreads();
    float d = x - mu;
    sh[tid] = d * d;
    __syncthreads();
    for (int o = 32; o > 0; o >>= 1) {
        if (lane < o) sh[tid] += sh[tid + o];
        __syncthreads();
    }
    float var = sh[tid & ~63] / 64.0f;
    out[off] = d * rsqrtf(var + 1e-5f) * g[lane] + beta[lane];
}

// ---------------- output projection: out[b,j,m] = zf[s,:] . out_W[j,:] + out_b[j] ----------------
__global__ __launch_bounds__(256) void out_kernel(
    const float* __restrict__ zf, const float* __restrict__ out_W,
    const float* __restrict__ out_b, float* __restrict__ out)
{
    const int j  = blockIdx.x;       // 0..95
    const int s0 = blockIdx.y * 8;   // 8 sequences per block
    float acc[8] = {0,0,0,0,0,0,0,0};
    const float4* Wr = (const float4*)(out_W + (size_t)j * (NPATCH*DMODEL));  // 32704 per row
    const int n4 = (NPATCH*DMODEL) / 4;  // 8176
    for (int kk = threadIdx.x; kk < n4; kk += 256) {
        float4 w = Wr[kk];
#pragma unroll
        for (int si = 0; si < 8; ++si) {
            float4 zv = ((const float4*)(zf + (size_t)(s0+si)*NPATCH*DMODEL))[kk];
            acc[si] += w.x*zv.x + w.y*zv.y + w.z*zv.z + w.w*zv.w;
        }
    }
    __shared__ float red[8][256];
#pragma unroll
    for (int si = 0; si < 8; ++si) red[si][threadIdx.x] = acc[si];
    __syncthreads();
    for (int off = 128; off > 0; off >>= 1) {
        if (threadIdx.x < off)
#pragma unroll
            for (int si = 0; si < 8; ++si)
                red[si][threadIdx.x] += red[si][threadIdx.x + off];
        __syncthreads();
    }
    if (threadIdx.x < 8) {
        int sI = s0 + threadIdx.x;
        int bI = sI >> 3, mI = sI & 7;
        out[(size_t)(bI*PREDL + j)*8 + mI] = red[threadIdx.x][0] + out_b[j];
    }
}

// ---------------- host ----------------
extern "C" void kernel_launch(void* const* d_in, const int* in_sizes, int n_in,
                              void* d_out, int out_size) {
    (void)in_sizes; (void)n_in; (void)out_size;
    const float* x_enc = (const float*)d_in[0];
    const float* in_W  = (const float*)d_in[4];
    const float* in_b  = (const float*)d_in[5];
    const float* Wq    = (const float*)d_in[6];
    const float* bq    = (const float*)d_in[7];
    const float* Wk    = (const float*)d_in[8];
    const float* bk    = (const float*)d_in[9];
    const float* Wv    = (const float*)d_in[10];
    const float* bv    = (const float*)d_in[11];
    const float* Wo    = (const float*)d_in[12];
    const float* bo    = (const float*)d_in[13];
    const float* c1W   = (const float*)d_in[14];
    const float* c1b   = (const float*)d_in[15];
    const float* c2W   = (const float*)d_in[16];
    const float* c2b   = (const float*)d_in[17];
    const float* ln1g  = (const float*)d_in[18];
    const float* ln1b  = (const float*)d_in[19];
    const float* ln2g  = (const float*)d_in[20];
    const float* ln2b  = (const float*)d_in[21];
    const float* lnfg  = (const float*)d_in[22];
    const float* lnfb  = (const float*)d_in[23];
    const float* outW  = (const float*)d_in[24];
    const float* outb  = (const float*)d_in[25];

    float *patchp, *zp, *qp, *kp, *vp, *aop, *tmpp, *x1p, *ffnp;
    int *idxp;
    cudaGetSymbolAddress((void**)&patchp, g_patch);
    cudaGetSymbolAddress((void**)&zp,  g_z);
    cudaGetSymbolAddress((void**)&qp,  g_q);
    cudaGetSymbolAddress((void**)&kp,  g_k);
    cudaGetSymbolAddress((void**)&vp,  g_v);
    cudaGetSymbolAddress((void**)&aop, g_ao);
    cudaGetSymbolAddress((void**)&tmpp,g_tmp);
    cudaGetSymbolAddress((void**)&x1p, g_x1);
    cudaGetSymbolAddress((void**)&ffnp,g_ffn);
    cudaGetSymbolAddress((void**)&idxp,g_sampidx);

    idx_kernel<<<2, 256>>>(idxp);
    patch_kernel<<<(ROWS*PATCH + 255)/256, 256>>>(x_enc, patchp);
    gemm_kernel<<<dim3(ROWS/64, 1), 256>>>(patchp, in_W, in_b, zp, PATCH, DMODEL, 0);

    for (int e = 0; e < 2; ++e) {
        gemm_kernel<<<dim3(ROWS/64, 1), 256>>>(zp, Wq + e*DMODEL*DMODEL, bq + e*DMODEL, qp, DMODEL, DMODEL, 0);
        gemm_kernel<<<dim3(ROWS/64, 1), 256>>>(zp, Wk + e*DMODEL*DMODEL, bk + e*DMODEL, kp, DMODEL, DMODEL, 0);
        gemm_kernel<<<dim3(ROWS/64, 1), 256>>>(zp, Wv + e*DMODEL*DMODEL, bv + e*DMODEL, vp, DMODEL, DMODEL, 0);
        attn_kernel<<<BMS*NHEAD, 256>>>(qp, kp, vp, idxp + e*NPATCH*UPART, aop);
        gemm_kernel<<<dim3(ROWS/64, 1), 256>>>(aop, Wo + e*DMODEL*DMODEL, bo + e*DMODEL, tmpp, DMODEL, DMODEL, 0);
        ln_kernel<<<ROWS/4, 256>>>(zp, tmpp, ln1g + e*DMODEL, ln1b + e*DMODEL, x1p);
        gemm_kernel<<<dim3(ROWS/64, 4), 256>>>(x1p, c1W + e*DFF*DMODEL, c1b + e*DFF, ffnp, DMODEL, DFF, 1);
        gemm_kernel<<<dim3(ROWS/64, 1), 256>>>(ffnp, c2W + e*DMODEL*DFF, c2b + e*DMODEL, tmpp, DFF, DMODEL, 0);
        ln_kernel<<<ROWS/4, 256>>>(x1p, tmpp, ln2g + e*DMODEL, ln2b + e*DMODEL, zp);
    }

    ln_kernel<<<ROWS/4, 256>>>(zp, (const float*)nullptr, lnfg, lnfb, x1p);
    out_kernel<<<dim3(PREDL, 8), 256>>>(x1p, outW, outb, (float*)d_out);
}

// round 12
// speedup vs baseline: 1.1939x; 1.1939x over previous
#include <cuda_runtime.h>
#include <math.h>
#include <stdint.h>

#define BMS     64        // B*M sequences
#define NPATCH  511
#define DMODEL  64
#define NHEAD   8
#define DHEAD   8
#define DFF     256
#define PATCH   16
#define PREDL   96
#define UPART   35
#define UTOP    35
#define ROWS    (BMS*NPATCH)   // 32704

// ---------------- scratch (device globals; no runtime allocation) ----------------
__device__ float g_patch[ROWS*PATCH];
__device__ float g_z  [ROWS*DMODEL];
__device__ float g_q  [ROWS*DMODEL];
__device__ float g_k  [ROWS*DMODEL];
__device__ float g_v  [ROWS*DMODEL];
__device__ float g_ao [ROWS*DMODEL];
__device__ float g_x1 [ROWS*DMODEL];
__device__ float g_ffn[ROWS*DFF];
__device__ int   g_sampidx[2*NPATCH*UPART];

// ---------------- Threefry-2x32 (JAX prng) ----------------
__device__ __forceinline__ void tf2x32(uint32_t k0, uint32_t k1,
                                       uint32_t x0, uint32_t x1,
                                       uint32_t& o0, uint32_t& o1) {
    uint32_t ks0 = k0, ks1 = k1, ks2 = k0 ^ k1 ^ 0x1BD11BDAu;
    x0 += ks0; x1 += ks1;
    const int RA[4] = {13,15,26,6};
    const int RB[4] = {17,29,16,24};
    uint32_t ks[3] = {ks0, ks1, ks2};
#pragma unroll
    for (int g = 0; g < 5; ++g) {
        const int* R = (g & 1) ? RB : RA;
#pragma unroll
        for (int i = 0; i < 4; ++i) {
            x0 += x1;
            x1 = (x1 << R[i]) | (x1 >> (32 - R[i]));
            x1 ^= x0;
        }
        x0 += ks[(g+1)%3];
        x1 += ks[(g+2)%3] + (uint32_t)(g+1);
    }
    o0 = x0; o1 = x1;
}

__global__ void idx_kernel(int* __restrict__ out) {
    int e = blockIdx.x;
    uint32_t ke0, ke1;
    tf2x32(0u, 1u, 0u, (uint32_t)e, ke0, ke1);          // fold_in(key(1), e)
    uint32_t k10, k11, k20, k21;
    tf2x32(ke0, ke1, 0u, 0u, k10, k11);                 // split -> k1
    tf2x32(ke0, ke1, 0u, 1u, k20, k21);                 // split -> k2
    const uint32_t span = 511u;
    uint32_t mult = (1u << 16) % span;                  // 128
    mult = (mult * mult) % span;                        // 32
    for (int i = threadIdx.x; i < NPATCH*UPART; i += blockDim.x) {
        uint32_t a0, a1, b0, b1;
        tf2x32(k10, k11, 0u, (uint32_t)i, a0, a1);
        tf2x32(k20, k21, 0u, (uint32_t)i, b0, b1);
        uint32_t hb = a0 ^ a1;
        uint32_t lb = b0 ^ b1;
        uint32_t off = ((hb % span) * mult + (lb % span)) % span;
        out[e*NPATCH*UPART + i] = (int)off;
    }
}

// ---------------- patch gather ----------------
__global__ void patch_kernel(const float* __restrict__ x_enc, float* __restrict__ outp) {
    int i = blockIdx.x * blockDim.x + threadIdx.x;
    if (i >= ROWS*PATCH) return;
    int p = i & 15;
    int n = (i >> 4) % NPATCH;
    int s = i / (NPATCH*PATCH);
    int b = s >> 3, m = s & 7;
    outp[i] = x_enc[(b*4096 + n*8 + p)*8 + m];
}

__device__ __forceinline__ float gelu_exact(float x) {
    return 0.5f * x * (1.0f + erff(x * 0.7071067811865476f));
}

// ---------------- small GEMM for in-projection (K=16, D=64) ----------------
__global__ __launch_bounds__(256) void gemm_kernel(
    const float* __restrict__ A, const float* __restrict__ W,
    const float* __restrict__ bias, float* __restrict__ C,
    int K, int D)
{
    __shared__ float As[16][68];
    __shared__ float Ws[16][68];
    const int row0 = blockIdx.x * 64;
    const int col0 = blockIdx.y * 64;
    const int tid = threadIdx.x;
    const int tx = tid & 15;
    const int ty = tid >> 4;
    float acc[4][4];
#pragma unroll
    for (int j = 0; j < 4; ++j) {
        float bv = bias[col0 + tx*4 + j];
#pragma unroll
        for (int i = 0; i < 4; ++i) acc[i][j] = bv;
    }
    const int lr = tid >> 2;
    const int lk = (tid & 3) * 4;
    for (int k0 = 0; k0 < K; k0 += 16) {
        float4 av4 = *(const float4*)&A[(size_t)(row0 + lr)*K + k0 + lk];
        float4 wv4 = *(const float4*)&W[(size_t)(col0 + lr)*K + k0 + lk];
        As[lk+0][lr] = av4.x; As[lk+1][lr] = av4.y; As[lk+2][lr] = av4.z; As[lk+3][lr] = av4.w;
        Ws[lk+0][lr] = wv4.x; Ws[lk+1][lr] = wv4.y; Ws[lk+2][lr] = wv4.z; Ws[lk+3][lr] = wv4.w;
        __syncthreads();
#pragma unroll
        for (int kl = 0; kl < 16; ++kl) {
            float4 a = *(const float4*)&As[kl][ty*4];
            float4 w = *(const float4*)&Ws[kl][tx*4];
            float av[4] = {a.x, a.y, a.z, a.w};
            float wv[4] = {w.x, w.y, w.z, w.w};
#pragma unroll
            for (int i = 0; i < 4; ++i)
#pragma unroll
                for (int j = 0; j < 4; ++j)
                    acc[i][j] += av[i] * wv[j];
        }
        __syncthreads();
    }
#pragma unroll
    for (int i = 0; i < 4; ++i) {
        int r = row0 + ty*4 + i;
#pragma unroll
        for (int j = 0; j < 4; ++j)
            C[(size_t)r*D + col0 + tx*4 + j] = acc[i][j];
    }
}

// ---------------- fused QKV projection (K=64, D=64 each), 64x64 tile ----------------
__global__ __launch_bounds__(256) void qkv_kernel(
    const float* __restrict__ A,
    const float* __restrict__ Wq, const float* __restrict__ bq,
    const float* __restrict__ Wk, const float* __restrict__ bk,
    const float* __restrict__ Wv, const float* __restrict__ bv,
    float* __restrict__ Qo, float* __restrict__ Ko, float* __restrict__ Vo)
{
    __shared__ float As[64][68];
    __shared__ float Ws[64][68];
    const int row0 = blockIdx.x * 64;
    const int tid = threadIdx.x;
    const int tx = tid & 15, ty = tid >> 4;
    const int lr = tid >> 2;          // 0..63
    const int lk = (tid & 3) * 16;    // 0,16,32,48

    // stage full A tile (64 rows x K=64)
#pragma unroll
    for (int i = 0; i < 4; ++i) {
        float4 a4 = *(const float4*)&A[(size_t)(row0 + lr)*64 + lk + i*4];
        As[lk+i*4+0][lr] = a4.x; As[lk+i*4+1][lr] = a4.y;
        As[lk+i*4+2][lr] = a4.z; As[lk+i*4+3][lr] = a4.w;
    }

    const float* Wm[3] = {Wq, Wk, Wv};
    const float* bm[3] = {bq, bk, bv};
    float*       Cm[3] = {Qo, Ko, Vo};

    for (int m = 0; m < 3; ++m) {
        const float* Wp = Wm[m];
#pragma unroll
        for (int i = 0; i < 4; ++i) {
            float4 w4 = *(const float4*)&Wp[(size_t)lr*64 + lk + i*4];
            Ws[lk+i*4+0][lr] = w4.x; Ws[lk+i*4+1][lr] = w4.y;
            Ws[lk+i*4+2][lr] = w4.z; Ws[lk+i*4+3][lr] = w4.w;
        }
        __syncthreads();
        float acc[4][4];
#pragma unroll
        for (int j = 0; j < 4; ++j) {
            float bv_ = bm[m][tx*4 + j];
#pragma unroll
            for (int i = 0; i < 4; ++i) acc[i][j] = bv_;
        }
#pragma unroll 16
        for (int kl = 0; kl < 64; ++kl) {
            float4 a = *(const float4*)&As[kl][ty*4];
            float4 w = *(const float4*)&Ws[kl][tx*4];
            float av[4] = {a.x, a.y, a.z, a.w};
            float wv[4] = {w.x, w.y, w.z, w.w};
#pragma unroll
            for (int i = 0; i < 4; ++i)
#pragma unroll
                for (int j = 0; j < 4; ++j)
                    acc[i][j] += av[i] * wv[j];
        }
        __syncthreads();   // before Ws overwrite next m
        float* Cp = Cm[m];
#pragma unroll
        for (int i = 0; i < 4; ++i) {
            int r = row0 + ty*4 + i;
            float4 o = make_float4(acc[i][0], acc[i][1], acc[i][2], acc[i][3]);
            *(float4*)&Cp[(size_t)r*64 + tx*4] = o;
        }
    }
}

// ------- fused GEMM(128x64) + residual + LayerNorm: C = LN(A@W^T + bias + R)*g + beta -------
__global__ __launch_bounds__(256) void gemm_ln_kernel(
    const float* __restrict__ A, const float* __restrict__ W,
    const float* __restrict__ bias, const float* __restrict__ R,
    const float* __restrict__ g, const float* __restrict__ beta,
    float* __restrict__ C, int K)
{
    __shared__ float As[32][132];
    __shared__ float Ws[32][68];
    const int row0 = blockIdx.x * 128;
    const int tid = threadIdx.x;
    const int tx = tid & 15, ty = tid >> 4;
    float acc[8][4];
    {
        float4 b4 = *(const float4*)&bias[tx*4];
#pragma unroll
        for (int i = 0; i < 8; ++i) {
            acc[i][0] = b4.x; acc[i][1] = b4.y; acc[i][2] = b4.z; acc[i][3] = b4.w;
        }
    }
    const int lrA = tid >> 1;                // 0..127
    const int lkA = (tid & 1) * 16;          // 0,16
    int garow = row0 + lrA; if (garow >= ROWS) garow = ROWS - 1;
    const int lrW = tid & 63;                // col 0..63
    const int lkW = (tid >> 6) * 8;          // 0,8,16,24

    for (int k0 = 0; k0 < K; k0 += 32) {
#pragma unroll
        for (int i = 0; i < 4; ++i) {
            float4 a4 = *(const float4*)&A[(size_t)garow*K + k0 + lkA + i*4];
            As[lkA+i*4+0][lrA] = a4.x; As[lkA+i*4+1][lrA] = a4.y;
            As[lkA+i*4+2][lrA] = a4.z; As[lkA+i*4+3][lrA] = a4.w;
        }
#pragma unroll
        for (int i = 0; i < 2; ++i) {
            float4 w4 = *(const float4*)&W[(size_t)lrW*K + k0 + lkW + i*4];
            Ws[lkW+i*4+0][lrW] = w4.x; Ws[lkW+i*4+1][lrW] = w4.y;
            Ws[lkW+i*4+2][lrW] = w4.z; Ws[lkW+i*4+3][lrW] = w4.w;
        }
        __syncthreads();
#pragma unroll
        for (int kl = 0; kl < 32; ++kl) {
            float4 a0 = *(const float4*)&As[kl][ty*8];
            float4 a1 = *(const float4*)&As[kl][ty*8+4];
            float4 w  = *(const float4*)&Ws[kl][tx*4];
            float av[8] = {a0.x,a0.y,a0.z,a0.w,a1.x,a1.y,a1.z,a1.w};
            float wv[4] = {w.x,w.y,w.z,w.w};
#pragma unroll
            for (int i = 0; i < 8; ++i)
#pragma unroll
                for (int j = 0; j < 4; ++j)
                    acc[i][j] += av[i] * wv[j];
        }
        __syncthreads();
    }

    // LN epilogue: each row (64 cols) is owned by 16 consecutive lanes (same ty)
    float4 g4  = *(const float4*)&g[tx*4];
    float4 be4 = *(const float4*)&beta[tx*4];
#pragma unroll
    for (int i = 0; i < 8; ++i) {
        int r = row0 + ty*8 + i;
        bool valid = (r < ROWS);
        float4 r4 = make_float4(0.f,0.f,0.f,0.f);
        if (valid) r4 = *(const float4*)&R[(size_t)r*64 + tx*4];
        float x0 = acc[i][0] + r4.x;
        float x1 = acc[i][1] + r4.y;
        float x2 = acc[i][2] + r4.z;
        float x3 = acc[i][3] + r4.w;
        float sum = x0 + x1 + x2 + x3;
#pragma unroll
        for (int off = 8; off > 0; off >>= 1)
            sum += __shfl_xor_sync(0xffffffffu, sum, off);
        float mu = sum * (1.0f/64.0f);
        float d0 = x0-mu, d1 = x1-mu, d2 = x2-mu, d3 = x3-mu;
        float vs = d0*d0 + d1*d1 + d2*d2 + d3*d3;
#pragma unroll
        for (int off = 8; off > 0; off >>= 1)
            vs += __shfl_xor_sync(0xffffffffu, vs, off);
        float inv = rsqrtf(vs * (1.0f/64.0f) + 1e-5f);
        if (valid) {
            float4 o;
            o.x = d0*inv*g4.x + be4.x;
            o.y = d1*inv*g4.y + be4.y;
            o.z = d2*inv*g4.z + be4.z;
            o.w = d3*inv*g4.w + be4.w;
            *(float4*)&C[(size_t)r*64 + tx*4] = o;
        }
    }
}

// ---------------- FFN1: C(Rx256) = gelu(A(Rx64) @ W(256x64)^T + b), 128x128 tile ----------------
__global__ __launch_bounds__(256) void ffn1_kernel(
    const float* __restrict__ A, const float* __restrict__ W,
    const float* __restrict__ bias, float* __restrict__ C)
{
    __shared__ float As[32][132];
    __shared__ float Ws[32][132];
    const int row0 = blockIdx.x * 128;
    const int col0 = blockIdx.y * 128;
    const int tid = threadIdx.x;
    const int tx = tid & 15, ty = tid >> 4;
    float acc[8][8];
    {
        float4 b0 = *(const float4*)&bias[col0 + tx*8];
        float4 b1 = *(const float4*)&bias[col0 + tx*8 + 4];
#pragma unroll
        for (int i = 0; i < 8; ++i) {
            acc[i][0]=b0.x; acc[i][1]=b0.y; acc[i][2]=b0.z; acc[i][3]=b0.w;
            acc[i][4]=b1.x; acc[i][5]=b1.y; acc[i][6]=b1.z; acc[i][7]=b1.w;
        }
    }
    const int lr = tid >> 1;           // 0..127
    const int lk = (tid & 1) * 16;     // 0,16
    int garow = row0 + lr; if (garow >= ROWS) garow = ROWS - 1;
    const int K = 64;

    for (int k0 = 0; k0 < K; k0 += 32) {
#pragma unroll
        for (int i = 0; i < 4; ++i) {
            float4 a4 = *(const float4*)&A[(size_t)garow*K + k0 + lk + i*4];
            As[lk+i*4+0][lr] = a4.x; As[lk+i*4+1][lr] = a4.y;
            As[lk+i*4+2][lr] = a4.z; As[lk+i*4+3][lr] = a4.w;
        }
#pragma unroll
        for (int i = 0; i < 4; ++i) {
            float4 w4 = *(const float4*)&W[(size_t)(col0 + lr)*K + k0 + lk + i*4];
            Ws[lk+i*4+0][lr] = w4.x; Ws[lk+i*4+1][lr] = w4.y;
            Ws[lk+i*4+2][lr] = w4.z; Ws[lk+i*4+3][lr] = w4.w;
        }
        __syncthreads();
#pragma unroll
        for (int kl = 0; kl < 32; ++kl) {
            float4 a0 = *(const float4*)&As[kl][ty*8];
            float4 a1 = *(const float4*)&As[kl][ty*8+4];
            float4 w0 = *(const float4*)&Ws[kl][tx*8];
            float4 w1 = *(const float4*)&Ws[kl][tx*8+4];
            float av[8] = {a0.x,a0.y,a0.z,a0.w,a1.x,a1.y,a1.z,a1.w};
            float wv[8] = {w0.x,w0.y,w0.z,w0.w,w1.x,w1.y,w1.z,w1.w};
#pragma unroll
            for (int i = 0; i < 8; ++i)
#pragma unroll
                for (int j = 0; j < 8; ++j)
                    acc[i][j] += av[i] * wv[j];
        }
        __syncthreads();
    }
#pragma unroll
    for (int i = 0; i < 8; ++i) {
        int r = row0 + ty*8 + i;
        if (r < ROWS) {
            float4 o0, o1;
            o0.x = gelu_exact(acc[i][0]); o0.y = gelu_exact(acc[i][1]);
            o0.z = gelu_exact(acc[i][2]); o0.w = gelu_exact(acc[i][3]);
            o1.x = gelu_exact(acc[i][4]); o1.y = gelu_exact(acc[i][5]);
            o1.z = gelu_exact(acc[i][6]); o1.w = gelu_exact(acc[i][7]);
            *(float4*)&C[(size_t)r*DFF + col0 + tx*8]     = o0;
            *(float4*)&C[(size_t)r*DFF + col0 + tx*8 + 4] = o1;
        }
    }
}

// ---------------- ProbSparse attention: one block per (s,h) ----------------
__global__ __launch_bounds__(256) void attn_kernel(
    const float* __restrict__ q, const float* __restrict__ k,
    const float* __restrict__ v, const int* __restrict__ sidx,
    float* __restrict__ ao)
{
    const int s = blockIdx.x >> 3;
    const int h = blockIdx.x & 7;
    const size_t base = (size_t)(s*NPATCH)*DMODEL + h*DHEAD;

    __shared__ float4 ksA[NPATCH], ksB[NPATCH], vsA[NPATCH], vsB[NPATCH];
    __shared__ float  sp[NPATCH];
    __shared__ float  rv[8];
    __shared__ int    ri[8];
    __shared__ int    topn[UTOP];
    __shared__ float  vmean[8];
    __shared__ float  sred[64];

    const int tid = threadIdx.x;
    const int wid = tid >> 5, lane = tid & 31;

    // load K/V head into shared
    float pv[8] = {0,0,0,0,0,0,0,0};
    for (int n = tid; n < NPATCH; n += 256) {
        const float4* kp = (const float4*)(k + base + (size_t)n*DMODEL);
        ksA[n] = kp[0]; ksB[n] = kp[1];
        const float4* vp = (const float4*)(v + base + (size_t)n*DMODEL);
        float4 v0 = vp[0], v1 = vp[1];
        vsA[n] = v0; vsB[n] = v1;
        pv[0]+=v0.x; pv[1]+=v0.y; pv[2]+=v0.z; pv[3]+=v0.w;
        pv[4]+=v1.x; pv[5]+=v1.y; pv[6]+=v1.z; pv[7]+=v1.w;
    }
    // vmean via warp shuffles
#pragma unroll
    for (int c = 0; c < 8; ++c)
#pragma unroll
        for (int off = 16; off > 0; off >>= 1)
            pv[c] += __shfl_xor_sync(0xffffffffu, pv[c], off);
    if (lane == 0)
#pragma unroll
        for (int c = 0; c < 8; ++c) sred[wid*8 + c] = pv[c];
    __syncthreads();
    if (tid < 8) {
        float sm = 0.f;
#pragma unroll
        for (int w = 0; w < 8; ++w) sm += sred[w*8 + tid];
        vmean[tid] = sm / 511.0f;
    }
    __syncthreads();

    // sparsity measure per query
    for (int n = tid; n < NPATCH; n += 256) {
        const float4* qp = (const float4*)(q + base + (size_t)n*DMODEL);
        float4 qa = qp[0], qb = qp[1];
        float mx = -INFINITY, sm = 0.f;
        const int* ip = sidx + n*UPART;
#pragma unroll 5
        for (int j = 0; j < UPART; ++j) {
            int kk = ip[j];
            float4 ka = ksA[kk], kb = ksB[kk];
            float d = qa.x*ka.x + qa.y*ka.y + qa.z*ka.z + qa.w*ka.w
                    + qb.x*kb.x + qb.y*kb.y + qb.z*kb.z + qb.w*kb.w;
            mx = fmaxf(mx, d);
            sm += d;
        }
        sp[n] = mx - sm / 511.0f;
    }
    __syncthreads();

    // top-35 (ties -> lower index, matching lax.top_k), warp-shuffle argmax
    for (int t = 0; t < UTOP; ++t) {
        float bv = -INFINITY; int bi = 0x7fffffff;
        for (int n = tid; n < NPATCH; n += 256)
            if (sp[n] > bv) { bv = sp[n]; bi = n; }
#pragma unroll
        for (int off = 16; off > 0; off >>= 1) {
            float ov = __shfl_xor_sync(0xffffffffu, bv, off);
            int   oi = __shfl_xor_sync(0xffffffffu, bi, off);
            if (ov > bv || (ov == bv && oi < bi)) { bv = ov; bi = oi; }
        }
        if (lane == 0) { rv[wid] = bv; ri[wid] = bi; }
        __syncthreads();
        if (tid == 0) {
            float best = rv[0]; int bsti = ri[0];
#pragma unroll
            for (int w = 1; w < 8; ++w)
                if (rv[w] > best || (rv[w] == best && ri[w] < bsti)) { best = rv[w]; bsti = ri[w]; }
            topn[t] = bsti; sp[bsti] = -INFINITY;
        }
        __syncthreads();
    }

    // default output: mean of V
    for (int i = tid; i < NPATCH*8; i += 256) {
        int n = i >> 3, c = i & 7;
        ao[base + (size_t)n*DMODEL + c] = vmean[c];
    }
    __syncthreads();

    // full attention for selected queries: one warp per query
    const float scale = 0.3535533905932738f;  // rsqrt(8)
    for (int t = wid; t < UTOP; t += 8) {
        int n = topn[t];
        const float4* qp = (const float4*)(q + base + (size_t)n*DMODEL);
        float4 qa = qp[0], qb = qp[1];
        float mx = -INFINITY;
        for (int kk = lane; kk < NPATCH; kk += 32) {
            float4 ka = ksA[kk], kb = ksB[kk];
            float d = (qa.x*ka.x + qa.y*ka.y + qa.z*ka.z + qa.w*ka.w
                     + qb.x*kb.x + qb.y*kb.y + qb.z*kb.z + qb.w*kb.w) * scale;
            mx = fmaxf(mx, d);
        }
#pragma unroll
        for (int off = 16; off > 0; off >>= 1)
            mx = fmaxf(mx, __shfl_xor_sync(0xffffffffu, mx, off));
        float sm = 0.f;
        float ac[8] = {0,0,0,0,0,0,0,0};
        for (int kk = lane; kk < NPATCH; kk += 32) {
            float4 ka = ksA[kk], kb = ksB[kk];
            float d = (qa.x*ka.x + qa.y*ka.y + qa.z*ka.z + qa.w*ka.w
                     + qb.x*kb.x + qb.y*kb.y + qb.z*kb.z + qb.w*kb.w) * scale;
            float e = expf(d - mx);
            sm += e;
            float4 va = vsA[kk], vb = vsB[kk];
            ac[0]+=e*va.x; ac[1]+=e*va.y; ac[2]+=e*va.z; ac[3]+=e*va.w;
            ac[4]+=e*vb.x; ac[5]+=e*vb.y; ac[6]+=e*vb.z; ac[7]+=e*vb.w;
        }
#pragma unroll
        for (int off = 16; off > 0; off >>= 1) {
            sm += __shfl_xor_sync(0xffffffffu, sm, off);
#pragma unroll
            for (int c = 0; c < 8; ++c)
                ac[c] += __shfl_xor_sync(0xffffffffu, ac[c], off);
        }
        if (lane == 0) {
            float inv = 1.0f / sm;
            float* op = ao + base + (size_t)n*DMODEL;
#pragma unroll
            for (int c = 0; c < 8; ++c) op[c] = ac[c] * inv;
        }
    }
}

// ---------------- standalone LayerNorm (final lnf only) ----------------
__global__ __launch_bounds__(256) void ln_kernel(
    const float* __restrict__ a,
    const float* __restrict__ g, const float* __restrict__ beta,
    float* __restrict__ out)
{
    const int tid  = threadIdx.x;
    const int row  = blockIdx.x*4 + (tid >> 6);
    const int lane = tid & 63;
    __shared__ float sh[256];
    const size_t off = (size_t)row*DMODEL + lane;
    float x = a[off];
    sh[tid] = x;
    __syncthreads();
    for (int o = 32; o > 0; o >>= 1) {
        if (lane < o) sh[tid] += sh[tid + o];
        __syncthreads();
    }
    float mu = sh[tid & ~63] / 64.0f;
    __syncthreads();
    float d = x - mu;
    sh[tid] = d * d;
    __syncthreads();
    for (int o = 32; o > 0; o >>= 1) {
        if (lane < o) sh[tid] += sh[tid + o];
        __syncthreads();
    }
    float var = sh[tid & ~63] / 64.0f;
    out[off] = d * rsqrtf(var + 1e-5f) * g[lane] + beta[lane];
}

// ---------------- output projection: 8j x 8s tiles ----------------
__global__ __launch_bounds__(256) void out_kernel(
    const float* __restrict__ zf, const float* __restrict__ out_W,
    const float* __restrict__ out_b, float* __restrict__ out)
{
    const int j0 = blockIdx.x * 8;   // grid.x = 12
    const int s0 = blockIdx.y * 8;   // grid.y = 8
    const int tid = threadIdx.x;
    const int wid = tid >> 5, lane = tid & 31;
    float acc[8][8];
#pragma unroll
    for (int j = 0; j < 8; ++j)
#pragma unroll
        for (int ss = 0; ss < 8; ++ss) acc[j][ss] = 0.f;

    const int n4 = (NPATCH*DMODEL) / 4;  // 8176
    for (int kk = tid; kk < n4; kk += 256) {
        float4 z4[8];
#pragma unroll
        for (int ss = 0; ss < 8; ++ss)
            z4[ss] = ((const float4*)(zf + (size_t)(s0+ss)*NPATCH*DMODEL))[kk];
#pragma unroll
        for (int j = 0; j < 8; ++j) {
            float4 w = ((const float4*)(out_W + (size_t)(j0+j)*NPATCH*DMODEL))[kk];
#pragma unroll
            for (int ss = 0; ss < 8; ++ss)
                acc[j][ss] += w.x*z4[ss].x + w.y*z4[ss].y + w.z*z4[ss].z + w.w*z4[ss].w;
        }
    }

    __shared__ float sred[8][8];  // [warp][s]
    for (int j = 0; j < 8; ++j) {
        float a[8];
#pragma unroll
        for (int ss = 0; ss < 8; ++ss) {
            a[ss] = acc[j][ss];
#pragma unroll
            for (int off = 16; off > 0; off >>= 1)
                a[ss] += __shfl_xor_sync(0xffffffffu, a[ss], off);
        }
        if (lane == 0)
#pragma unroll
            for (int ss = 0; ss < 8; ++ss) sred[wid][ss] = a[ss];
        __syncthreads();
        if (tid < 8) {
            float sum = 0.f;
#pragma unroll
            for (int w = 0; w < 8; ++w) sum += sred[w][tid];
            int sI = s0 + tid;
            int bI = sI >> 3, mI = sI & 7;
            out[(size_t)(bI*PREDL + (j0+j))*8 + mI] = sum + out_b[j0+j];
        }
        __syncthreads();
    }
}

// ---------------- host ----------------
extern "C" void kernel_launch(void* const* d_in, const int* in_sizes, int n_in,
                              void* d_out, int out_size) {
    (void)in_sizes; (void)n_in; (void)out_size;
    const float* x_enc = (const float*)d_in[0];
    const float* in_W  = (const float*)d_in[4];
    const float* in_b  = (const float*)d_in[5];
    const float* Wq    = (const float*)d_in[6];
    const float* bq    = (const float*)d_in[7];
    const float* Wk    = (const float*)d_in[8];
    const float* bk    = (const float*)d_in[9];
    const float* Wv    = (const float*)d_in[10];
    const float* bv    = (const float*)d_in[11];
    const float* Wo    = (const float*)d_in[12];
    const float* bo    = (const float*)d_in[13];
    const float* c1W   = (const float*)d_in[14];
    const float* c1b   = (const float*)d_in[15];
    const float* c2W   = (const float*)d_in[16];
    const float* c2b   = (const float*)d_in[17];
    const float* ln1g  = (const float*)d_in[18];
    const float* ln1b  = (const float*)d_in[19];
    const float* ln2g  = (const float*)d_in[20];
    const float* ln2b  = (const float*)d_in[21];
    const float* lnfg  = (const float*)d_in[22];
    const float* lnfb  = (const float*)d_in[23];
    const float* outW  = (const float*)d_in[24];
    const float* outb  = (const float*)d_in[25];

    float *patchp, *zp, *qp, *kp, *vp, *aop, *x1p, *ffnp;
    int *idxp;
    cudaGetSymbolAddress((void**)&patchp, g_patch);
    cudaGetSymbolAddress((void**)&zp,  g_z);
    cudaGetSymbolAddress((void**)&qp,  g_q);
    cudaGetSymbolAddress((void**)&kp,  g_k);
    cudaGetSymbolAddress((void**)&vp,  g_v);
    cudaGetSymbolAddress((void**)&aop, g_ao);
    cudaGetSymbolAddress((void**)&x1p, g_x1);
    cudaGetSymbolAddress((void**)&ffnp,g_ffn);
    cudaGetSymbolAddress((void**)&idxp,g_sampidx);

    idx_kernel<<<2, 256>>>(idxp);
    patch_kernel<<<(ROWS*PATCH + 255)/256, 256>>>(x_enc, patchp);
    gemm_kernel<<<dim3(ROWS/64, 1), 256>>>(patchp, in_W, in_b, zp, PATCH, DMODEL);

    const int GRID128 = (ROWS + 127) / 128;  // 256

    for (int e = 0; e < 2; ++e) {
        qkv_kernel<<<ROWS/64, 256>>>(zp,
            Wq + e*DMODEL*DMODEL, bq + e*DMODEL,
            Wk + e*DMODEL*DMODEL, bk + e*DMODEL,
            Wv + e*DMODEL*DMODEL, bv + e*DMODEL,
            qp, kp, vp);
        attn_kernel<<<BMS*NHEAD, 256>>>(qp, kp, vp, idxp + e*NPATCH*UPART, aop);
        // x1 = LN1(z + ao@Wo^T + bo)
        gemm_ln_kernel<<<GRID128, 256>>>(aop, Wo + e*DMODEL*DMODEL, bo + e*DMODEL,
                                         zp, ln1g + e*DMODEL, ln1b + e*DMODEL, x1p, DMODEL);
        ffn1_kernel<<<dim3(GRID128, 2), 256>>>(x1p, c1W + e*DFF*DMODEL, c1b + e*DFF, ffnp);
        // z = LN2(x1 + ffn@c2W^T + c2b)
        gemm_ln_kernel<<<GRID128, 256>>>(ffnp, c2W + e*DMODEL*DFF, c2b + e*DMODEL,
                                         x1p, ln2g + e*DMODEL, ln2b + e*DMODEL, zp, DFF);
    }

    ln_kernel<<<ROWS/4, 256>>>(zp, lnfg, lnfb, x1p);
    out_kernel<<<dim3(PREDL/8, 8), 256>>>(x1p, outW, outb, (float*)d_out);
}